// round 12
// baseline (speedup 1.0000x reference)
#include <cuda_runtime.h>
#include <cuda_bf16.h>
#include <cstdint>

#define NCTA 128
#define THR  512

// word-offsets in dynamic smem
#define W_X    0          // GEMM1 X bufs: 3 x (128 rows x 40 words)
#define XBUF   5120
#define W_DW   15360      // GEMM1 dw bufs: 3 x (hi 64x20 + lo 64x20)
#define DWBUF  2560
#define W_U    0          // GEMM2 uw bufs: 3 x (hi 128x40 + lo 128x40), reuse region
#define UBUF   10240
#define W_DSM  30720      // 128 x 66 f32
#define W_RH   39168      // R hi: 128 rows x 36 words (shorts stride 72)
#define W_RL   43776
#define SMEM_SZ (48384*4)

__device__ unsigned short g_dwh[64*4096], g_dwl[64*4096];
__device__ unsigned short g_uwh[4096*64], g_uwl[4096*64];

static __device__ __forceinline__ uint32_t pk2(float lo, float hi) {
    uint32_t r; asm("cvt.rn.bf16x2.f32 %0, %1, %2;" : "=r"(r) : "f"(hi), "f"(lo)); return r;
}
static __device__ __forceinline__ void bmma(float d[4], const uint32_t a[4],
                                            uint32_t b0, uint32_t b1) {
    asm("mma.sync.aligned.m16n8k16.row.col.f32.bf16.bf16.f32 "
        "{%0,%1,%2,%3},{%4,%5,%6,%7},{%8,%9},{%0,%1,%2,%3};"
        : "+f"(d[0]), "+f"(d[1]), "+f"(d[2]), "+f"(d[3])
        : "r"(a[0]), "r"(a[1]), "r"(a[2]), "r"(a[3]), "r"(b0), "r"(b1));
}
static __device__ __forceinline__ uint32_t smem_u32(const void* p) {
    uint32_t a;
    asm("{ .reg .u64 t; cvta.to.shared.u64 t, %1; cvt.u32.u64 %0, t; }" : "=r"(a) : "l"(p));
    return a;
}
static __device__ __forceinline__ void cpa(uint32_t s, const void* g) {
    asm volatile("cp.async.ca.shared.global [%0], [%1], 16;" :: "r"(s), "l"(g) : "memory");
}
#define CPC()  asm volatile("cp.async.commit_group;" ::: "memory")
#define CPW1() asm volatile("cp.async.wait_group 1;" ::: "memory")
#define CPW0() asm volatile("cp.async.wait_group 0;" ::: "memory")

__global__ void kprep(const float* __restrict__ dw, const float* __restrict__ uw) {
    int i = blockIdx.x * 256 + threadIdx.x;
    float v = (i < 262144) ? dw[i] : uw[i - 262144];
    __nv_bfloat16 hb = __float2bfloat16(v);
    float l = v - __bfloat162float(hb);
    __nv_bfloat16 lb = __float2bfloat16(l);
    unsigned short hu = *(unsigned short*)&hb, lu = *(unsigned short*)&lb;
    if (i < 262144) { g_dwh[i] = hu; g_dwl[i] = lu; }
    else            { g_uwh[i - 262144] = hu; g_uwl[i - 262144] = lu; }
}

__global__ __launch_bounds__(THR, 1) void moe_mma(
    const float* __restrict__ x, const float* __restrict__ tv,
    const long long* __restrict__ ti, float* __restrict__ out)
{
    extern __shared__ uint32_t sm[];
    float* smf = (float*)sm;
    const uint32_t su = smem_u32(sm);
    const int tid = threadIdx.x, wid = tid >> 5, lane = tid & 31;
    const int lr = lane >> 2, lc = lane & 3;
    const int h = wid >> 3;                       // GEMM1 k-half
    const int team = wid & 7, tm = team >> 1, tn = team & 1;   // m32 x n32 team tile
    const int wm = wid >> 2, wn = wid & 3;        // GEMM2 mapping
    const int row0 = blockIdx.x * 128;

    const float4* x4 = (const float4*)x;

    // ---- stage GEMM1 chunks 0,1 (start DRAM early) ----
    #pragma unroll
    for (int cc = 0; cc < 2; cc++) {
        uint32_t xb = su + (W_X + cc * XBUF) * 4;
        #pragma unroll
        for (int j = 0; j < 2; j++) {
            int f = tid + j * THR, r = f >> 3, q = f & 7;
            cpa(xb + (r*40 + q*4)*4, x4 + (size_t)(row0 + r)*1024 + cc*8 + q);
        }
        uint32_t db = su + (W_DW + cc * DWBUF) * 4;
        int hf = tid >> 8, n = (tid >> 2) & 63, q = tid & 3;
        const unsigned short* src = (hf ? g_dwl : g_dwh) + n*4096 + cc*32 + q*8;
        cpa(db + (hf*1280 + n*20 + q*4)*4, src);
        CPC();
    }

    // ---- pack top-k indices (int32/int64 auto-detect, in-bounds) ----
    uint32_t plo = 0, phi = 0;
    {
        const int* t32b = (const int*)ti;
        bool is64 = ((t32b[1]|t32b[3]|t32b[5]|t32b[7]|t32b[9]|t32b[11]|t32b[13]|t32b[15]) == 0);
        if (tid < 128) {
            int row = row0 + tid;
            if (is64) {
                const long long* t = ti + (size_t)row * 8;
                #pragma unroll
                for (int k = 0; k < 4; k++) { plo |= ((uint32_t)t[k]&63u)<<(8*k); phi |= ((uint32_t)t[4+k]&63u)<<(8*k); }
            } else {
                const int* t = t32b + (size_t)row * 8;
                #pragma unroll
                for (int k = 0; k < 4; k++) { plo |= ((uint32_t)t[k]&63u)<<(8*k); phi |= ((uint32_t)t[4+k]&63u)<<(8*k); }
            }
        }
    }
    // zero R region (9216 words)
    #pragma unroll
    for (int j = 0; j < 18; j++) sm[W_RH + tid + j*THR] = 0;

    // ================== GEMM1: split-K x2, 128 chunks of 32 cols ==================
    float acc[2][4][4];
    #pragma unroll
    for (int i = 0; i < 2; i++)
        #pragma unroll
        for (int nt = 0; nt < 4; nt++) { acc[i][nt][0]=acc[i][nt][1]=acc[i][nt][2]=acc[i][nt][3]=0.f; }

    #pragma unroll 1
    for (int c = 0; c < 128; c++) {
        if (c < 127) CPW1(); else CPW0();   // chunk c staged
        __syncthreads();                    // all done computing c-1 -> buf (c+2)%3 free
        if (c + 2 < 128) {                  // stage chunk c+2
            int b2 = (c + 2) % 3;
            uint32_t xb = su + (W_X + b2 * XBUF) * 4;
            #pragma unroll
            for (int j = 0; j < 2; j++) {
                int f = tid + j * THR, r = f >> 3, q = f & 7;
                cpa(xb + (r*40 + q*4)*4, x4 + (size_t)(row0 + r)*1024 + (c+2)*8 + q);
            }
            uint32_t db = su + (W_DW + b2 * DWBUF) * 4;
            int hf = tid >> 8, n = (tid >> 2) & 63, q = tid & 3;
            const unsigned short* src = (hf ? g_dwl : g_dwh) + n*4096 + (c+2)*32 + q*8;
            cpa(db + (hf*1280 + n*20 + q*4)*4, src);
            CPC();
        }
        if ((c & 1) == h) {
            const int bp = c % 3;
            const uint32_t xw = W_X + bp * XBUF;
            const uint32_t bh = W_DW + bp * DWBUF;
            const uint32_t bl = bh + 1280;
            #pragma unroll
            for (int s = 0; s < 2; s++) {
                uint32_t B0h[4], B1h[4], B0l[4], B1l[4];
                #pragma unroll
                for (int nt = 0; nt < 4; nt++) {
                    uint32_t wb = (tn*32 + nt*8 + lr)*20 + s*8 + lc;
                    B0h[nt] = sm[bh+wb]; B1h[nt] = sm[bh+wb+4];
                    B0l[nt] = sm[bl+wb]; B1l[nt] = sm[bl+wb+4];
                }
                uint32_t ah[2][4], al[2][4];
                #pragma unroll
                for (int i = 0; i < 2; i++)
                    #pragma unroll
                    for (int j = 0; j < 4; j++) {
                        int r  = tm*32 + i*16 + lr + (j & 1)*8;
                        int ko = s*16 + lc*2 + (j >> 1)*8;
                        float2 f = *(float2*)&smf[xw + r*40 + ko];
                        uint32_t hh = pk2(f.x, f.y);
                        float lx = f.x - __uint_as_float(hh << 16);
                        float ly = f.y - __uint_as_float(hh & 0xffff0000u);
                        ah[i][j] = hh; al[i][j] = pk2(lx, ly);
                    }
                #pragma unroll
                for (int i = 0; i < 2; i++)
                    #pragma unroll
                    for (int nt = 0; nt < 4; nt++) bmma(acc[i][nt], ah[i], B0h[nt], B1h[nt]);
                #pragma unroll
                for (int i = 0; i < 2; i++)
                    #pragma unroll
                    for (int nt = 0; nt < 4; nt++) bmma(acc[i][nt], ah[i], B0l[nt], B1l[nt]);
                #pragma unroll
                for (int i = 0; i < 2; i++)
                    #pragma unroll
                    for (int nt = 0; nt < 4; nt++) bmma(acc[i][nt], al[i], B0h[nt], B1h[nt]);
            }
        }
    }

    // ---- transition: stage GEMM2 chunks 0,1 NOW (hides DRAM behind reduce) ----
    __syncthreads();   // compute of chunk 127 done; buffer region free
    #pragma unroll
    for (int cc = 0; cc < 2; cc++) {
        uint32_t ub = su + (W_U + cc * UBUF) * 4;
        #pragma unroll
        for (int j = 0; j < 4; j++) {
            int f = tid + j * THR;           // 0..2047
            int hf = f >> 10, g = f & 1023, n = g >> 3, q = g & 7;
            const unsigned short* src = (hf ? g_uwl : g_uwh) + (size_t)(cc*128 + n)*64 + q*8;
            cpa(ub + (hf*5120 + n*40 + q*4)*4, src);
        }
        CPC();
    }

    // ---- reduce 2 k-halves into Dsm ----
    if (h == 0) {
        #pragma unroll
        for (int i = 0; i < 2; i++)
            #pragma unroll
            for (int nt = 0; nt < 4; nt++) {
                uint32_t wd = W_DSM + (tm*32 + i*16 + lr)*66 + tn*32 + nt*8 + lc*2;
                *(float2*)&sm[wd]       = make_float2(acc[i][nt][0], acc[i][nt][1]);
                *(float2*)&sm[wd + 528] = make_float2(acc[i][nt][2], acc[i][nt][3]);
            }
    }
    __syncthreads();
    if (h == 1) {
        #pragma unroll
        for (int i = 0; i < 2; i++)
            #pragma unroll
            for (int nt = 0; nt < 4; nt++) {
                uint32_t wd = W_DSM + (tm*32 + i*16 + lr)*66 + tn*32 + nt*8 + lc*2;
                float2 u0 = *(float2*)&sm[wd], u1 = *(float2*)&sm[wd + 528];
                u0.x += acc[i][nt][0]; u0.y += acc[i][nt][1];
                u1.x += acc[i][nt][2]; u1.y += acc[i][nt][3];
                *(float2*)&sm[wd]       = u0;
                *(float2*)&sm[wd + 528] = u1;
            }
    }
    __syncthreads();

    // ---- gather * scale -> sparse R (bf16 split) ----
    if (tid < 128) {
        const float* tvr = tv + (size_t)(row0 + tid)*8;
        #pragma unroll
        for (int k = 0; k < 8; k++) {
            uint32_t idx = ((k < 4 ? plo : phi) >> (8*(k&3))) & 63u;
            float v = smf[W_DSM + tid*66 + idx] * tvr[k];
            __nv_bfloat16 hb = __float2bfloat16(v);
            float l = v - __bfloat162float(hb);
            __nv_bfloat16 lb = __float2bfloat16(l);
            ((unsigned short*)&sm[W_RH])[tid*72 + idx] = *(unsigned short*)&hb;
            ((unsigned short*)&sm[W_RL])[tid*72 + idx] = *(unsigned short*)&lb;
        }
    }
    __syncthreads();

    // ---- R fragments register-resident (m32 per warp) ----
    uint32_t Ah[2][4][4], Al[2][4][4];
    #pragma unroll
    for (int i = 0; i < 2; i++)
        #pragma unroll
        for (int s = 0; s < 4; s++) {
            uint32_t wa = ((wm*2+i)*16 + lr)*36 + s*8 + lc;
            Ah[i][s][0] = sm[W_RH+wa]; Ah[i][s][1] = sm[W_RH+wa+288]; Ah[i][s][2] = sm[W_RH+wa+4]; Ah[i][s][3] = sm[W_RH+wa+292];
            Al[i][s][0] = sm[W_RL+wa]; Al[i][s][1] = sm[W_RL+wa+288]; Al[i][s][2] = sm[W_RL+wa+4]; Al[i][s][3] = sm[W_RL+wa+292];
        }

    // ========== GEMM2: out[128,4096] = R @ uw^T, 32 chunks of 128 cols ==========
    #pragma unroll 1
    for (int ch = 0; ch < 32; ch++) {
        if (ch < 31) CPW1(); else CPW0();
        __syncthreads();
        if (ch + 2 < 32) {
            uint32_t ub = su + (W_U + ((ch + 2) % 3) * UBUF) * 4;
            #pragma unroll
            for (int j = 0; j < 4; j++) {
                int f = tid + j * THR;
                int hf = f >> 10, g = f & 1023, n = g >> 3, q = g & 7;
                const unsigned short* src = (hf ? g_uwl : g_uwh) + (size_t)((ch+2)*128 + n)*64 + q*8;
                cpa(ub + (hf*5120 + n*40 + q*4)*4, src);
            }
            CPC();
        }
        const uint32_t uh = W_U + (ch % 3) * UBUF;
        const uint32_t ul = uh + 5120;
        #pragma unroll
        for (int tt = 0; tt < 4; tt++) {
            int t = wn*4 + tt;
            float d0[4] = {0.f,0.f,0.f,0.f}, d1[4] = {0.f,0.f,0.f,0.f};
            #pragma unroll
            for (int s = 0; s < 4; s++) {
                uint32_t wb = (t*8 + lr)*40 + s*8 + lc;
                uint32_t bh0 = sm[uh+wb], bh1 = sm[uh+wb+4];
                uint32_t bl0 = sm[ul+wb], bl1 = sm[ul+wb+4];
                bmma(d0, Ah[0][s], bh0, bh1);
                bmma(d0, Ah[0][s], bl0, bl1);
                bmma(d0, Al[0][s], bh0, bh1);
                bmma(d1, Ah[1][s], bh0, bh1);
                bmma(d1, Ah[1][s], bl0, bl1);
                bmma(d1, Al[1][s], bh0, bh1);
            }
            size_t o0 = (size_t)(row0 + (wm*2+0)*16 + lr)*4096 + ch*128 + t*8 + lc*2;
            size_t o1 = (size_t)(row0 + (wm*2+1)*16 + lr)*4096 + ch*128 + t*8 + lc*2;
            *(float2*)&out[o0]          = make_float2(d0[0], d0[1]);
            *(float2*)&out[o0 + 8*4096] = make_float2(d0[2], d0[3]);
            *(float2*)&out[o1]          = make_float2(d1[0], d1[1]);
            *(float2*)&out[o1 + 8*4096] = make_float2(d1[2], d1[3]);
        }
    }
}

extern "C" void kernel_launch(void* const* d_in, const int* in_sizes, int n_in,
                              void* d_out, int out_size)
{
    const float*     x  = (const float*)d_in[0];      // [16384,4096]
    const float*     dw = (const float*)d_in[1];      // [64,4096]
    const float*     uw = (const float*)d_in[2];      // [4096,64]
    const float*     tv = (const float*)d_in[3];      // [16384,8]
    const long long* ti = (const long long*)d_in[4];  // [16384,8] i32/i64

    cudaFuncSetAttribute(moe_mma, cudaFuncAttributeMaxDynamicSharedMemorySize, SMEM_SZ);
    kprep<<<2048, 256>>>(dw, uw);
    moe_mma<<<NCTA, THR, SMEM_SZ>>>(x, tv, ti, (float*)d_out);
}